// round 1
// baseline (speedup 1.0000x reference)
#include <cuda_runtime.h>
#include <cuda_bf16.h>
#include <math.h>

// ---------------- problem constants ----------------
#define NN   8192      // nodes
#define NE   32768     // edges
#define NB   64        // graphs
#define DF   64        // hidden D
#define NFI  32        // node feature dim
#define EFI  16        // edge feature dim
#define NOUT 12
#define TMP  3         // message passing steps
#define TS2S 12        // set2set steps

// T columns: [ W2t (4096) | bias-term (64) | W_hh (192) ]
#define TC   4352

// ---------------- device scratch (no allocs allowed) ----------------
__device__ float g_ed[NE * DF];          // relu(edge MLP layer 1)     8 MB
__device__ float g_W2t[DF * TC];         // packed right operand       1.1 MB
__device__ float g_T[(size_t)NN * TC];   // per-node transform         142.6 MB
__device__ float g_h[NN * DF];           // node hidden state          2 MB
__device__ float g_agg[NN * DF];         // scattered messages         2 MB
__device__ float g_gi[NN * 3 * DF];      // agg @ W_ih                 6 MB
__device__ int   g_segoff[NB + 1];

__device__ __forceinline__ float sigmoidf_(float x) { return 1.0f / (1.0f + expf(-x)); }

// ---------------- prep: pack W2t = [perm(W_ee2) | b_ee2 layout | W_hh] ----------------
// g_W2t[j*TC + c]:
//   c in [0,4096):  k=c>>6, i=c&63  ->  W_ee2[k*4096 + i*64 + j]
//   c in [4096,4160): i=c-4096      ->  b_ee2[i*64 + j]
//   c in [4160,4352): g=c-4160      ->  W_hh[j*192 + g]
__global__ void prep_w2t_kernel(const float* __restrict__ W_ee2,
                                const float* __restrict__ b_ee2,
                                const float* __restrict__ W_hh) {
    int idx = blockIdx.x * blockDim.x + threadIdx.x;
    if (idx >= DF * TC) return;
    int j = idx / TC;
    int c = idx % TC;
    float v;
    if (c < 4096) {
        int k = c >> 6, i = c & 63;
        v = W_ee2[k * 4096 + i * 64 + j];
    } else if (c < 4160) {
        int i = c - 4096;
        v = b_ee2[i * 64 + j];
    } else {
        int g = c - 4160;
        v = W_hh[j * 192 + g];
    }
    g_W2t[idx] = v;
}

// ---------------- edge encoder layer 1: ed = relu(ef @ W_ee1 + b_ee1) ----------------
__global__ void edge_enc_kernel(const float* __restrict__ ef,
                                const float* __restrict__ W1,
                                const float* __restrict__ b1) {
    __shared__ float w1s[EFI * DF];   // 16*64
    __shared__ float b1s[DF];
    __shared__ float efs[4][EFI];
    int tid = threadIdx.x;
    int e0 = blockIdx.x * 4;
    for (int it = tid; it < EFI * DF; it += 256) w1s[it] = W1[it];
    if (tid < DF) b1s[tid] = b1[tid];
    if (tid < 4 * EFI) efs[tid / EFI][tid % EFI] = ef[(e0 + tid / EFI) * EFI + (tid % EFI)];
    __syncthreads();
    int le = tid / DF;       // 0..3
    int d  = tid % DF;
    float acc = b1s[d];
#pragma unroll
    for (int f = 0; f < EFI; f++) acc += efs[le][f] * w1s[f * DF + d];
    g_ed[(e0 + le) * DF + d] = fmaxf(acc, 0.0f);
}

// ---------------- input projection: h = nf @ W_in + b_in ----------------
__global__ void input_proj_kernel(const float* __restrict__ nf,
                                  const float* __restrict__ W,
                                  const float* __restrict__ b) {
    __shared__ float ws[NFI * DF];    // 32*64
    __shared__ float bs[DF];
    __shared__ float nfs[4][NFI];
    int tid = threadIdx.x;
    int n0 = blockIdx.x * 4;
    for (int it = tid; it < NFI * DF; it += 256) ws[it] = W[it];
    if (tid < DF) bs[tid] = b[tid];
    if (tid < 4 * NFI) nfs[tid / NFI][tid % NFI] = nf[(n0 + tid / NFI) * NFI + (tid % NFI)];
    __syncthreads();
    int ln = tid / DF;
    int d  = tid % DF;
    float acc = bs[d];
#pragma unroll
    for (int f = 0; f < NFI; f++) acc += nfs[ln][f] * ws[f * DF + d];
    g_h[(n0 + ln) * DF + d] = acc;
}

// ---------------- segment offsets: batch is sorted ----------------
__global__ void segoff_kernel(const int* __restrict__ batch) {
    int g = threadIdx.x;
    if (g > NB) return;
    if (g == NB) { g_segoff[NB] = NN; return; }
    int lo = 0, hi = NN;
    while (lo < hi) { int mid = (lo + hi) >> 1; if (batch[mid] < g) lo = mid + 1; else hi = mid; }
    g_segoff[g] = lo;
}

// ---------------- SGEMM: C[M,Nc] = A[M,64] @ B[64,Nc] (no bias) ----------------
// block = 256 threads, 64x64 tile, full K=64 in one slab.
__global__ void sgemm64_kernel(const float* __restrict__ A,
                               const float* __restrict__ Bm,
                               float* __restrict__ C, int Ncols) {
    __shared__ float As[64][64];   // transposed: As[k][m]
    __shared__ float Bs[64][64];
    int tid = threadIdx.x;
    int m0 = blockIdx.y * 64;
    int n0 = blockIdx.x * 64;
#pragma unroll
    for (int it = 0; it < 4; it++) {
        int idx = tid + it * 256;            // 0..1023
        int row = idx >> 4;                  // 0..63
        int k4  = (idx & 15) << 2;
        float4 v = *(const float4*)&A[(size_t)(m0 + row) * 64 + k4];
        As[k4 + 0][row] = v.x; As[k4 + 1][row] = v.y;
        As[k4 + 2][row] = v.z; As[k4 + 3][row] = v.w;
    }
#pragma unroll
    for (int it = 0; it < 4; it++) {
        int idx = tid + it * 256;
        int krow = idx >> 4;
        int c4   = (idx & 15) << 2;
        *(float4*)&Bs[krow][c4] = *(const float4*)&Bm[(size_t)krow * Ncols + n0 + c4];
    }
    __syncthreads();
    int tx4 = (tid & 15) << 2;
    int ty4 = (tid >> 4) << 2;
    float acc[4][4] = {};
#pragma unroll
    for (int k = 0; k < 64; k++) {
        float4 a = *(const float4*)&As[k][ty4];
        float4 b = *(const float4*)&Bs[k][tx4];
        acc[0][0] += a.x * b.x; acc[0][1] += a.x * b.y; acc[0][2] += a.x * b.z; acc[0][3] += a.x * b.w;
        acc[1][0] += a.y * b.x; acc[1][1] += a.y * b.y; acc[1][2] += a.y * b.z; acc[1][3] += a.y * b.w;
        acc[2][0] += a.z * b.x; acc[2][1] += a.z * b.y; acc[2][2] += a.z * b.z; acc[2][3] += a.z * b.w;
        acc[3][0] += a.w * b.x; acc[3][1] += a.w * b.y; acc[3][2] += a.w * b.z; acc[3][3] += a.w * b.w;
    }
#pragma unroll
    for (int r = 0; r < 4; r++) {
        *(float4*)&C[(size_t)(m0 + ty4 + r) * Ncols + n0 + tx4] =
            make_float4(acc[r][0], acc[r][1], acc[r][2], acc[r][3]);
    }
}

// ---------------- zero agg ----------------
__global__ void zero_agg_kernel() {
    int idx = blockIdx.x * blockDim.x + threadIdx.x;
    if (idx < NN * DF) g_agg[idx] = 0.0f;
}

// ---------------- edge message + scatter ----------------
// msg_e[i] = sum_k ed[e,k] * T[src, k*64+i]  + T[src, 4096+i]   (bias-term)
// atomicAdd into agg[tgt, i]
__global__ void edge_msg_kernel(const int* __restrict__ Esrc,
                                const int* __restrict__ Etgt) {
    __shared__ float eds[4][DF];
    int tid = threadIdx.x;
    int le  = tid / DF;                 // local edge 0..3
    int i   = tid % DF;
    int e   = blockIdx.x * 4 + le;
    eds[le][i] = g_ed[e * DF + i];
    __syncthreads();
    int src = Esrc[e];
    int tgt = Etgt[e];
    const float* Trow = &g_T[(size_t)src * TC];
    float acc = Trow[4096 + i];
#pragma unroll
    for (int k = 0; k < DF; k++) acc += eds[le][k] * Trow[k * DF + i];
    atomicAdd(&g_agg[tgt * DF + i], acc);
}

// ---------------- GRU elementwise update (gh lives in T[:,4160:]) ----------------
__global__ void gru_kernel(const float* __restrict__ b_ih,
                           const float* __restrict__ b_hh) {
    int idx = blockIdx.x * blockDim.x + threadIdx.x;
    if (idx >= NN * DF) return;
    int n = idx / DF;
    int d = idx % DF;
    const float* Trow = &g_T[(size_t)n * TC + 4160];
    float gh_r = Trow[d]         + b_hh[d];
    float gh_z = Trow[64 + d]    + b_hh[64 + d];
    float gh_n = Trow[128 + d]   + b_hh[128 + d];
    const float* gi = &g_gi[n * 192];
    float gi_r = gi[d]       + b_ih[d];
    float gi_z = gi[64 + d]  + b_ih[64 + d];
    float gi_n = gi[128 + d] + b_ih[128 + d];
    float r = sigmoidf_(gi_r + gh_r);
    float z = sigmoidf_(gi_z + gh_z);
    float nn = tanhf(gi_n + r * gh_n);
    float h = g_h[idx];
    g_h[idx] = (1.0f - z) * nn + z * h;
}

// ---------------- fused Set2Set (12 steps) + output head; one block per graph ----------------
#define MAXSEG 2048
__global__ void set2set_kernel(const float* __restrict__ Wl_ih,
                               const float* __restrict__ Wl_hh,
                               const float* __restrict__ bl_ih,
                               const float* __restrict__ bl_hh,
                               const float* __restrict__ W_out,
                               const float* __restrict__ b_out,
                               float* __restrict__ out) {
    __shared__ float q[DF], hs[DF], cs[DF], qstar[2 * DF], gates[4 * DF];
    __shared__ float evals[MAXSEG];
    __shared__ float redmax[8], redsum[8];
    int b   = blockIdx.x;
    int tid = threadIdx.x;
    int lane = tid & 31, w = tid >> 5;
    int start = g_segoff[b], end = g_segoff[b + 1];
    int cnt = end - start;
    if (tid < DF) { hs[tid] = 0.0f; cs[tid] = 0.0f; }
    if (tid < 2 * DF) qstar[tid] = 0.0f;
    __syncthreads();

    for (int s = 0; s < TS2S; s++) {
        // LSTM gates: 256 threads, one gate output each
        float acc = bl_ih[tid] + bl_hh[tid];
#pragma unroll 4
        for (int j = 0; j < 2 * DF; j++) acc += qstar[j] * Wl_ih[j * 256 + tid];
#pragma unroll 4
        for (int j = 0; j < DF; j++)     acc += hs[j] * Wl_hh[j * 256 + tid];
        gates[tid] = acc;
        __syncthreads();
        if (tid < DF) {
            float i_ = gates[tid], f_ = gates[64 + tid], g_ = gates[128 + tid], o_ = gates[192 + tid];
            float cc = sigmoidf_(f_) * cs[tid] + sigmoidf_(i_) * tanhf(g_);
            cs[tid] = cc;
            float hh = sigmoidf_(o_) * tanhf(cc);
            hs[tid] = hh;
            q[tid] = hh;
        }
        __syncthreads();
        if (s == TS2S - 1) break;   // final attention never consumed (q_star[:, :D] = q)

        if (cnt > 0) {
            // e_n = <x_n, q>, one node per warp round-robin
            for (int idx = w; idx < cnt; idx += 8) {
                const float* xr = &g_h[(size_t)(start + idx) * DF];
                float p = xr[lane] * q[lane] + xr[lane + 32] * q[lane + 32];
#pragma unroll
                for (int o = 16; o; o >>= 1) p += __shfl_xor_sync(0xffffffffu, p, o);
                if (lane == 0) evals[idx] = p;
            }
            __syncthreads();
            // segment max
            float m = -INFINITY;
            for (int idx = tid; idx < cnt; idx += 256) m = fmaxf(m, evals[idx]);
#pragma unroll
            for (int o = 16; o; o >>= 1) m = fmaxf(m, __shfl_xor_sync(0xffffffffu, m, o));
            if (lane == 0) redmax[w] = m;
            __syncthreads();
            float emax = redmax[0];
#pragma unroll
            for (int k = 1; k < 8; k++) emax = fmaxf(emax, redmax[k]);
            // exp + denom
            float dsum = 0.0f;
            for (int idx = tid; idx < cnt; idx += 256) {
                float ex = expf(evals[idx] - emax);
                evals[idx] = ex;
                dsum += ex;
            }
#pragma unroll
            for (int o = 16; o; o >>= 1) dsum += __shfl_xor_sync(0xffffffffu, dsum, o);
            if (lane == 0) redsum[w] = dsum;
            __syncthreads();
            float denom = 0.0f;
#pragma unroll
            for (int k = 0; k < 8; k++) denom += redsum[k];
            // r[d] = sum_n a_n * x[n,d]
            if (tid < DF) {
                float r = 0.0f;
                for (int idx = 0; idx < cnt; idx++)
                    r += evals[idx] * g_h[(size_t)(start + idx) * DF + tid];
                qstar[64 + tid] = r / denom;
                qstar[tid] = q[tid];
            }
        } else {
            if (tid < DF) { qstar[tid] = q[tid]; qstar[64 + tid] = 0.0f; }
        }
        __syncthreads();
    }

    // output head: out[b] = q @ W_out + b_out
    if (tid < NOUT) {
        float acc = b_out[tid];
#pragma unroll
        for (int d = 0; d < DF; d++) acc += q[d] * W_out[d * NOUT + tid];
        out[b * NOUT + tid] = acc;
    }
}

// ---------------- launcher ----------------
extern "C" void kernel_launch(void* const* d_in, const int* in_sizes, int n_in,
                              void* d_out, int out_size) {
    const float* node_features = (const float*)d_in[0];
    const float* edge_features = (const float*)d_in[1];
    const int*   Esrc          = (const int*)d_in[2];
    const int*   Etgt          = (const int*)d_in[3];
    const int*   batch         = (const int*)d_in[4];
    const float* W_in  = (const float*)d_in[5];
    const float* b_in  = (const float*)d_in[6];
    const float* W_ee1 = (const float*)d_in[7];
    const float* b_ee1 = (const float*)d_in[8];
    const float* W_ee2 = (const float*)d_in[9];
    const float* b_ee2 = (const float*)d_in[10];
    const float* W_ih  = (const float*)d_in[11];
    const float* W_hh  = (const float*)d_in[12];
    const float* b_ih  = (const float*)d_in[13];
    const float* b_hh  = (const float*)d_in[14];
    const float* Wl_ih = (const float*)d_in[15];
    const float* Wl_hh = (const float*)d_in[16];
    const float* bl_ih = (const float*)d_in[17];
    const float* bl_hh = (const float*)d_in[18];
    const float* W_out = (const float*)d_in[19];
    const float* b_out = (const float*)d_in[20];
    float* out = (float*)d_out;

    // scratch pointers via symbol address (not an allocation)
    float *p_h, *p_W2t, *p_T, *p_agg, *p_gi;
    cudaGetSymbolAddress((void**)&p_h,   g_h);
    cudaGetSymbolAddress((void**)&p_W2t, g_W2t);
    cudaGetSymbolAddress((void**)&p_T,   g_T);
    cudaGetSymbolAddress((void**)&p_agg, g_agg);
    cudaGetSymbolAddress((void**)&p_gi,  g_gi);

    // --- prep ---
    prep_w2t_kernel<<<(DF * TC + 255) / 256, 256>>>(W_ee2, b_ee2, W_hh);
    edge_enc_kernel<<<NE / 4, 256>>>(edge_features, W_ee1, b_ee1);
    input_proj_kernel<<<NN / 4, 256>>>(node_features, W_in, b_in);
    segoff_kernel<<<1, 128>>>(batch);

    // --- message passing ---
    for (int t = 0; t < TMP; t++) {
        dim3 gT(TC / 64, NN / 64);
        sgemm64_kernel<<<gT, 256>>>(p_h, p_W2t, p_T, TC);
        zero_agg_kernel<<<(NN * DF + 255) / 256, 256>>>();
        edge_msg_kernel<<<NE / 4, 256>>>(Esrc, Etgt);
        dim3 gGi(192 / 64, NN / 64);
        sgemm64_kernel<<<gGi, 256>>>(p_agg, W_ih, p_gi, 192);
        gru_kernel<<<(NN * DF + 255) / 256, 256>>>(b_ih, b_hh);
    }

    // --- set2set + output head ---
    set2set_kernel<<<NB, 256>>>(Wl_ih, Wl_hh, bl_ih, bl_hh, W_out, b_out, out);
}

// round 4
// speedup vs baseline: 1.0710x; 1.0710x over previous
#include <cuda_runtime.h>
#include <cuda_bf16.h>
#include <math.h>
#include <mma.h>

using namespace nvcuda;

// ---------------- problem constants ----------------
#define NN   8192      // nodes
#define NE   32768     // edges
#define NB   64        // graphs
#define DF   64        // hidden D
#define NFI  32        // node feature dim
#define EFI  16        // edge feature dim
#define NOUT 12
#define TMP  3         // message passing steps
#define TS2S 12        // set2set steps

// T columns: [ W2t (4096) | bias-term (64) | W_hh (192) ]
#define TC   4352

// ---------------- device scratch (no allocs allowed) ----------------
__device__ __align__(16) float g_ed[NE * DF];          // relu(edge MLP layer 1)     8 MB
__device__ __align__(16) float g_W2t[DF * TC];         // packed right operand       1.1 MB
__device__ __align__(16) float g_T[(size_t)NN * TC];   // per-node transform         142.6 MB
__device__ __align__(16) float g_h[NN * DF];           // node hidden state          2 MB
__device__ __align__(16) float g_agg[NN * DF];         // scattered messages         2 MB
__device__ __align__(16) float g_gi[NN * 3 * DF];      // agg @ W_ih                 6 MB
__device__ int   g_segoff[NB + 1];
// edge sorting by src
__device__ int   g_scnt[NN];             // per-src counts
__device__ int   g_scur[NN];             // running offsets
__device__ int   g_sorted[NE];           // edge ids sorted by src

__device__ __forceinline__ float sigmoidf_(float x) { return 1.0f / (1.0f + expf(-x)); }

// ---------------- prep: pack W2t = [perm(W_ee2) | b_ee2 layout | W_hh] ----------------
__global__ void prep_w2t_kernel(const float* __restrict__ W_ee2,
                                const float* __restrict__ b_ee2,
                                const float* __restrict__ W_hh) {
    int idx = blockIdx.x * blockDim.x + threadIdx.x;
    if (idx >= DF * TC) return;
    int j = idx / TC;
    int c = idx % TC;
    float v;
    if (c < 4096) {
        int k = c >> 6, i = c & 63;
        v = W_ee2[k * 4096 + i * 64 + j];
    } else if (c < 4160) {
        int i = c - 4096;
        v = b_ee2[i * 64 + j];
    } else {
        int g = c - 4160;
        v = W_hh[j * 192 + g];
    }
    g_W2t[idx] = v;
}

// ---------------- edge encoder layer 1: ed = relu(ef @ W_ee1 + b_ee1) ----------------
__global__ void edge_enc_kernel(const float* __restrict__ ef,
                                const float* __restrict__ W1,
                                const float* __restrict__ b1) {
    __shared__ float w1s[EFI * DF];
    __shared__ float b1s[DF];
    __shared__ float efs[4][EFI];
    int tid = threadIdx.x;
    int e0 = blockIdx.x * 4;
    for (int it = tid; it < EFI * DF; it += 256) w1s[it] = W1[it];
    if (tid < DF) b1s[tid] = b1[tid];
    if (tid < 4 * EFI) efs[tid / EFI][tid % EFI] = ef[(e0 + tid / EFI) * EFI + (tid % EFI)];
    __syncthreads();
    int le = tid / DF;
    int d  = tid % DF;
    float acc = b1s[d];
#pragma unroll
    for (int f = 0; f < EFI; f++) acc += efs[le][f] * w1s[f * DF + d];
    g_ed[(e0 + le) * DF + d] = fmaxf(acc, 0.0f);
}

// ---------------- input projection: h = nf @ W_in + b_in ----------------
__global__ void input_proj_kernel(const float* __restrict__ nf,
                                  const float* __restrict__ W,
                                  const float* __restrict__ b) {
    __shared__ float ws[NFI * DF];
    __shared__ float bs[DF];
    __shared__ float nfs[4][NFI];
    int tid = threadIdx.x;
    int n0 = blockIdx.x * 4;
    for (int it = tid; it < NFI * DF; it += 256) ws[it] = W[it];
    if (tid < DF) bs[tid] = b[tid];
    if (tid < 4 * NFI) nfs[tid / NFI][tid % NFI] = nf[(n0 + tid / NFI) * NFI + (tid % NFI)];
    __syncthreads();
    int ln = tid / DF;
    int d  = tid % DF;
    float acc = bs[d];
#pragma unroll
    for (int f = 0; f < NFI; f++) acc += nfs[ln][f] * ws[f * DF + d];
    g_h[(n0 + ln) * DF + d] = acc;
}

// ---------------- segment offsets: batch is sorted ----------------
__global__ void segoff_kernel(const int* __restrict__ batch) {
    int g = threadIdx.x;
    if (g > NB) return;
    if (g == NB) { g_segoff[NB] = NN; return; }
    int lo = 0, hi = NN;
    while (lo < hi) { int mid = (lo + hi) >> 1; if (batch[mid] < g) lo = mid + 1; else hi = mid; }
    g_segoff[g] = lo;
}

// ---------------- edge sort by src: count / scan / scatter ----------------
__global__ void count_kernel(const int* __restrict__ Esrc) {
    int e = blockIdx.x * blockDim.x + threadIdx.x;
    if (e < NE) atomicAdd(&g_scnt[Esrc[e]], 1);
}

__global__ void scan_kernel() {
    __shared__ int part[1024];
    int tid = threadIdx.x;
    int loc[8]; int s = 0;
#pragma unroll
    for (int i = 0; i < 8; i++) { loc[i] = s; s += g_scnt[tid * 8 + i]; }
    part[tid] = s;
    __syncthreads();
    for (int off = 1; off < 1024; off <<= 1) {
        int t = (tid >= off) ? part[tid - off] : 0;
        __syncthreads();
        part[tid] += t;
        __syncthreads();
    }
    int excl = tid ? part[tid - 1] : 0;
#pragma unroll
    for (int i = 0; i < 8; i++) g_scur[tid * 8 + i] = excl + loc[i];
}

__global__ void scatter_kernel(const int* __restrict__ Esrc) {
    int e = blockIdx.x * blockDim.x + threadIdx.x;
    if (e >= NE) return;
    int p = atomicAdd(&g_scur[Esrc[e]], 1);
    g_sorted[p] = e;
}

// ---------------- 3xTF32 tensor-core GEMM: C[M,Nc] = A[M,64] @ B[64,Nc] ----------------
// 64x64 tile per block, 128 threads (4 warps, each 32x32), K=64 (8 mma k-steps).
// Error compensation: x = hi + lo with hi = tf32(x), lo = tf32(x - hi);
// acc += a_lo*b_hi + a_hi*b_lo + a_hi*b_hi  -> ~fp32 accuracy on tensor cores.
__global__ void gemm_tf32x3_kernel(const float* __restrict__ A,
                                   const float* __restrict__ Bm,
                                   float* __restrict__ C, int Ncols) {
    __shared__ float As[64][68];
    __shared__ float Bs[64][68];
    int tid = threadIdx.x;                 // 0..127
    int m0 = blockIdx.y * 64;
    int n0 = blockIdx.x * 64;
    // load raw fp32 tiles
#pragma unroll
    for (int it = 0; it < 8; it++) {
        int idx = tid + it * 128;          // 0..1023
        int row = idx >> 4;                // 0..63
        int c4  = (idx & 15) << 2;
        float4 va = *(const float4*)&A[(size_t)(m0 + row) * 64 + c4];
        As[row][c4 + 0] = va.x; As[row][c4 + 1] = va.y;
        As[row][c4 + 2] = va.z; As[row][c4 + 3] = va.w;
        float4 vb = *(const float4*)&Bm[(size_t)row * Ncols + n0 + c4];
        Bs[row][c4 + 0] = vb.x; Bs[row][c4 + 1] = vb.y;
        Bs[row][c4 + 2] = vb.z; Bs[row][c4 + 3] = vb.w;
    }
    __syncthreads();
    int warp = tid >> 5;
    int wm = warp >> 1;
    int wn = warp & 1;
    wmma::fragment<wmma::accumulator, 16, 16, 8, float> acc[2][2];
#pragma unroll
    for (int i = 0; i < 2; i++)
#pragma unroll
        for (int j = 0; j < 2; j++) wmma::fill_fragment(acc[i][j], 0.0f);
#pragma unroll
    for (int ks = 0; ks < 8; ks++) {
        wmma::fragment<wmma::matrix_a, 16, 16, 8, wmma::precision::tf32, wmma::row_major> ah[2], al[2];
        wmma::fragment<wmma::matrix_b, 16, 16, 8, wmma::precision::tf32, wmma::row_major> bh[2], bl[2];
#pragma unroll
        for (int i = 0; i < 2; i++) {
            wmma::load_matrix_sync(ah[i], &As[wm * 32 + i * 16][ks * 8], 68);
#pragma unroll
            for (int t = 0; t < ah[i].num_elements; t++) {
                float x  = ah[i].x[t];
                float hi = wmma::__float_to_tf32(x);
                al[i].x[t] = wmma::__float_to_tf32(x - hi);
                ah[i].x[t] = hi;
            }
        }
#pragma unroll
        for (int j = 0; j < 2; j++) {
            wmma::load_matrix_sync(bh[j], &Bs[ks * 8][wn * 32 + j * 16], 68);
#pragma unroll
            for (int t = 0; t < bh[j].num_elements; t++) {
                float x  = bh[j].x[t];
                float hi = wmma::__float_to_tf32(x);
                bl[j].x[t] = wmma::__float_to_tf32(x - hi);
                bh[j].x[t] = hi;
            }
        }
#pragma unroll
        for (int i = 0; i < 2; i++)
#pragma unroll
            for (int j = 0; j < 2; j++) {
                wmma::mma_sync(acc[i][j], al[i], bh[j], acc[i][j]);
                wmma::mma_sync(acc[i][j], ah[i], bl[j], acc[i][j]);
                wmma::mma_sync(acc[i][j], ah[i], bh[j], acc[i][j]);
            }
    }
#pragma unroll
    for (int i = 0; i < 2; i++)
#pragma unroll
        for (int j = 0; j < 2; j++)
            wmma::store_matrix_sync(
                &C[(size_t)(m0 + wm * 32 + i * 16) * Ncols + n0 + wn * 32 + j * 16],
                acc[i][j], Ncols, wmma::mem_row_major);
}

// ---------------- edge message + scatter (src-sorted order) ----------------
__global__ void edge_msg_kernel(const int* __restrict__ Esrc,
                                const int* __restrict__ Etgt) {
    __shared__ float eds[4][DF];
    int tid = threadIdx.x;
    int le  = tid / DF;                 // local edge 0..3
    int i   = tid % DF;
    int e   = g_sorted[blockIdx.x * 4 + le];
    eds[le][i] = g_ed[e * DF + i];
    int src = Esrc[e];
    int tgt = Etgt[e];
    __syncthreads();
    const float* Trow = &g_T[(size_t)src * TC];
    float acc = Trow[4096 + i];
#pragma unroll
    for (int k = 0; k < DF; k++) acc += eds[le][k] * Trow[k * DF + i];
    atomicAdd(&g_agg[tgt * DF + i], acc);
}

// ---------------- GRU elementwise update (gh lives in T[:,4160:]) ----------------
__global__ void gru_kernel(const float* __restrict__ b_ih,
                           const float* __restrict__ b_hh) {
    int idx = blockIdx.x * blockDim.x + threadIdx.x;
    if (idx >= NN * DF) return;
    int n = idx / DF;
    int d = idx % DF;
    const float* Trow = &g_T[(size_t)n * TC + 4160];
    float gh_r = Trow[d]         + b_hh[d];
    float gh_z = Trow[64 + d]    + b_hh[64 + d];
    float gh_n = Trow[128 + d]   + b_hh[128 + d];
    const float* gi = &g_gi[n * 192];
    float gi_r = gi[d]       + b_ih[d];
    float gi_z = gi[64 + d]  + b_ih[64 + d];
    float gi_n = gi[128 + d] + b_ih[128 + d];
    float r = sigmoidf_(gi_r + gh_r);
    float z = sigmoidf_(gi_z + gh_z);
    float nn = tanhf(gi_n + r * gh_n);
    float h = g_h[idx];
    g_h[idx] = (1.0f - z) * nn + z * h;
}

// ---------------- fused Set2Set (12 steps) + output head; one block per graph ----------------
#define MAXSEG 2048
__global__ void set2set_kernel(const float* __restrict__ Wl_ih,
                               const float* __restrict__ Wl_hh,
                               const float* __restrict__ bl_ih,
                               const float* __restrict__ bl_hh,
                               const float* __restrict__ W_out,
                               const float* __restrict__ b_out,
                               float* __restrict__ out) {
    __shared__ float q[DF], hs[DF], cs[DF], qstar[2 * DF], gates[4 * DF];
    __shared__ float evals[MAXSEG];
    __shared__ float redmax[8], redsum[8];
    int b   = blockIdx.x;
    int tid = threadIdx.x;
    int lane = tid & 31, w = tid >> 5;
    int start = g_segoff[b], end = g_segoff[b + 1];
    int cnt = end - start;
    if (tid < DF) { hs[tid] = 0.0f; cs[tid] = 0.0f; }
    if (tid < 2 * DF) qstar[tid] = 0.0f;
    __syncthreads();

    for (int s = 0; s < TS2S; s++) {
        float acc = bl_ih[tid] + bl_hh[tid];
#pragma unroll 4
        for (int j = 0; j < 2 * DF; j++) acc += qstar[j] * Wl_ih[j * 256 + tid];
#pragma unroll 4
        for (int j = 0; j < DF; j++)     acc += hs[j] * Wl_hh[j * 256 + tid];
        gates[tid] = acc;
        __syncthreads();
        if (tid < DF) {
            float i_ = gates[tid], f_ = gates[64 + tid], g_ = gates[128 + tid], o_ = gates[192 + tid];
            float cc = sigmoidf_(f_) * cs[tid] + sigmoidf_(i_) * tanhf(g_);
            cs[tid] = cc;
            float hh = sigmoidf_(o_) * tanhf(cc);
            hs[tid] = hh;
            q[tid] = hh;
        }
        __syncthreads();
        if (s == TS2S - 1) break;

        if (cnt > 0) {
            for (int idx = w; idx < cnt; idx += 8) {
                const float* xr = &g_h[(size_t)(start + idx) * DF];
                float p = xr[lane] * q[lane] + xr[lane + 32] * q[lane + 32];
#pragma unroll
                for (int o = 16; o; o >>= 1) p += __shfl_xor_sync(0xffffffffu, p, o);
                if (lane == 0) evals[idx] = p;
            }
            __syncthreads();
            float m = -INFINITY;
            for (int idx = tid; idx < cnt; idx += 256) m = fmaxf(m, evals[idx]);
#pragma unroll
            for (int o = 16; o; o >>= 1) m = fmaxf(m, __shfl_xor_sync(0xffffffffu, m, o));
            if (lane == 0) redmax[w] = m;
            __syncthreads();
            float emax = redmax[0];
#pragma unroll
            for (int k = 1; k < 8; k++) emax = fmaxf(emax, redmax[k]);
            float dsum = 0.0f;
            for (int idx = tid; idx < cnt; idx += 256) {
                float ex = expf(evals[idx] - emax);
                evals[idx] = ex;
                dsum += ex;
            }
#pragma unroll
            for (int o = 16; o; o >>= 1) dsum += __shfl_xor_sync(0xffffffffu, dsum, o);
            if (lane == 0) redsum[w] = dsum;
            __syncthreads();
            float denom = 0.0f;
#pragma unroll
            for (int k = 0; k < 8; k++) denom += redsum[k];
            if (tid < DF) {
                float r = 0.0f;
                for (int idx = 0; idx < cnt; idx++)
                    r += evals[idx] * g_h[(size_t)(start + idx) * DF + tid];
                qstar[64 + tid] = r / denom;
                qstar[tid] = q[tid];
            }
        } else {
            if (tid < DF) { qstar[tid] = q[tid]; qstar[64 + tid] = 0.0f; }
        }
        __syncthreads();
    }

    if (tid < NOUT) {
        float acc = b_out[tid];
#pragma unroll
        for (int d = 0; d < DF; d++) acc += q[d] * W_out[d * NOUT + tid];
        out[b * NOUT + tid] = acc;
    }
}

// ---------------- launcher ----------------
extern "C" void kernel_launch(void* const* d_in, const int* in_sizes, int n_in,
                              void* d_out, int out_size) {
    const float* node_features = (const float*)d_in[0];
    const float* edge_features = (const float*)d_in[1];
    const int*   Esrc          = (const int*)d_in[2];
    const int*   Etgt          = (const int*)d_in[3];
    const int*   batch         = (const int*)d_in[4];
    const float* W_in  = (const float*)d_in[5];
    const float* b_in  = (const float*)d_in[6];
    const float* W_ee1 = (const float*)d_in[7];
    const float* b_ee1 = (const float*)d_in[8];
    const float* W_ee2 = (const float*)d_in[9];
    const float* b_ee2 = (const float*)d_in[10];
    const float* W_ih  = (const float*)d_in[11];
    const float* W_hh  = (const float*)d_in[12];
    const float* b_ih  = (const float*)d_in[13];
    const float* b_hh  = (const float*)d_in[14];
    const float* Wl_ih = (const float*)d_in[15];
    const float* Wl_hh = (const float*)d_in[16];
    const float* bl_ih = (const float*)d_in[17];
    const float* bl_hh = (const float*)d_in[18];
    const float* W_out = (const float*)d_in[19];
    const float* b_out = (const float*)d_in[20];
    float* out = (float*)d_out;

    float *p_h, *p_W2t, *p_T, *p_agg, *p_gi;
    int *p_scnt;
    cudaGetSymbolAddress((void**)&p_h,    g_h);
    cudaGetSymbolAddress((void**)&p_W2t,  g_W2t);
    cudaGetSymbolAddress((void**)&p_T,    g_T);
    cudaGetSymbolAddress((void**)&p_agg,  g_agg);
    cudaGetSymbolAddress((void**)&p_gi,   g_gi);
    cudaGetSymbolAddress((void**)&p_scnt, g_scnt);

    // --- prep ---
    prep_w2t_kernel<<<(DF * TC + 255) / 256, 256>>>(W_ee2, b_ee2, W_hh);
    edge_enc_kernel<<<NE / 4, 256>>>(edge_features, W_ee1, b_ee1);
    input_proj_kernel<<<NN / 4, 256>>>(node_features, W_in, b_in);
    segoff_kernel<<<1, 128>>>(batch);
    // edge sort by src (one-time)
    cudaMemsetAsync(p_scnt, 0, NN * sizeof(int));
    count_kernel<<<NE / 256, 256>>>(Esrc);
    scan_kernel<<<1, 1024>>>();
    scatter_kernel<<<NE / 256, 256>>>(Esrc);

    // --- message passing ---
    for (int t = 0; t < TMP; t++) {
        dim3 gT(TC / 64, NN / 64);
        gemm_tf32x3_kernel<<<gT, 128>>>(p_h, p_W2t, p_T, TC);
        cudaMemsetAsync(p_agg, 0, NN * DF * sizeof(float));
        edge_msg_kernel<<<NE / 4, 256>>>(Esrc, Etgt);
        dim3 gGi(192 / 64, NN / 64);
        gemm_tf32x3_kernel<<<gGi, 128>>>(p_agg, W_ih, p_gi, 192);
        gru_kernel<<<(NN * DF + 255) / 256, 256>>>(b_ih, b_hh);
    }

    // --- set2set + output head ---
    set2set_kernel<<<NB, 256>>>(Wl_ih, Wl_hh, bl_ih, bl_hh, W_out, b_out, out);
}